// round 6
// baseline (speedup 1.0000x reference)
#include <cuda_runtime.h>
#include <cuda_bf16.h>
#include <cstdint>

#define NMAX 1000000
#define NBUCKETS 65536            // top 16 bits of the 47-bit key (bits 31..46)
#define CAP 128                   // max bucket size (lambda ~15-30; 128 is >>18 sigma)
#define WPB 8                     // warps per block in bucket kernels

// ---------------------------------------------------------------------------
// Static device scratch (no allocations allowed anywhere)
// ---------------------------------------------------------------------------
__device__ uint64_t g_keys[NMAX];        // decode output (unordered)
__device__ uint64_t g_bkeys[NMAX];       // bucket-distributed keys (+first bit)
__device__ uint32_t g_bvals[NMAX];       // bucket-distributed original indices
__device__ int      g_newc[(size_t)NMAX * 4];
__device__ uint32_t g_hist[NBUCKETS];    // zero-init; reset by scan each call
__device__ uint32_t g_off[NBUCKETS + 1];
__device__ uint32_t g_cursor[NBUCKETS];
__device__ uint32_t g_uniq[NBUCKETS];
__device__ uint32_t g_ubase[NBUCKETS + 1];

#define KEYMASK ((1ull << 47) - 1ull)
#define FIRSTBIT (1ull << 63)

// ---------------------------------------------------------------------------
// Packed f32x2 helpers (FFMA2 — PTX-only on sm_103a)
// ---------------------------------------------------------------------------
__device__ __forceinline__ void fma2(uint64_t& d, uint64_t a, uint64_t b, uint64_t c) {
    asm("fma.rn.f32x2 %0, %1, %2, %3;" : "=l"(d) : "l"(a), "l"(b), "l"(c));
}
__device__ __forceinline__ uint64_t dup2(float x) {
    uint64_t r; uint32_t u = __float_as_uint(x);
    asm("mov.b64 %0, {%1, %1};" : "=l"(r) : "r"(u));
    return r;
}
__device__ __forceinline__ uint64_t pack2(float lo, float hi) {
    uint64_t r;
    asm("mov.b64 %0, {%1, %2};" : "=l"(r) : "r"(__float_as_uint(lo)), "r"(__float_as_uint(hi)));
    return r;
}
__device__ __forceinline__ void unpack2(uint64_t v, float& lo, float& hi) {
    uint32_t a, b;
    asm("mov.b64 {%0, %1}, %2;" : "=r"(a), "=r"(b) : "l"(v));
    lo = __uint_as_float(a); hi = __uint_as_float(b);
}

// ---------------------------------------------------------------------------
// Kernel 1: MLP decode (f32x2, LDS.128 weight loads) + key + histogram + zero
// ---------------------------------------------------------------------------
__global__ void __launch_bounds__(256)
decode_kernel(const float* __restrict__ feats,
              const int*   __restrict__ coords,
              const int*   __restrict__ mask,
              const float* __restrict__ W1, const float* __restrict__ b1,
              const float* __restrict__ W2, const float* __restrict__ b2,
              const float* __restrict__ W3, const float* __restrict__ b3,
              float* __restrict__ out, int n)
{
    __shared__ __align__(16) float sW1[64 * 32];
    __shared__ __align__(16) float sW2[32 * 16];
    __shared__ __align__(16) float sW3[16 * 3];
    __shared__ __align__(16) float sb1[32];
    __shared__ __align__(16) float sb2[16];
    __shared__ __align__(16) float sb3[4];

    for (int t = threadIdx.x; t < 64 * 32; t += blockDim.x) sW1[t] = W1[t];
    for (int t = threadIdx.x; t < 32 * 16; t += blockDim.x) sW2[t] = W2[t];
    for (int t = threadIdx.x; t < 16 * 3;  t += blockDim.x) sW3[t] = W3[t];
    if (threadIdx.x < 32) sb1[threadIdx.x] = b1[threadIdx.x];
    if (threadIdx.x < 16) sb2[threadIdx.x] = b2[threadIdx.x];
    if (threadIdx.x < 3)  sb3[threadIdx.x] = b3[threadIdx.x];
    __syncthreads();

    int i = blockIdx.x * blockDim.x + threadIdx.x;
    if (i >= n) return;

    // ---- layer 1: 64 -> 32 (packed pairs; weights via LDS.128) ----
    uint64_t acc[16];
#pragma unroll
    for (int p = 0; p < 16; p++) acc[p] = pack2(sb1[2 * p], sb1[2 * p + 1]);

    const ulonglong2* w1q = reinterpret_cast<const ulonglong2*>(sW1); // [64][8]
    const float4* f4 = reinterpret_cast<const float4*>(feats) + (size_t)i * 16;
#pragma unroll
    for (int k4 = 0; k4 < 16; k4++) {
        float4 f = f4[k4];
        uint64_t a0 = dup2(f.x), a1 = dup2(f.y), a2 = dup2(f.z), a3 = dup2(f.w);
        const ulonglong2* r0 = &w1q[(k4 * 4 + 0) * 8];
        const ulonglong2* r1 = &w1q[(k4 * 4 + 1) * 8];
        const ulonglong2* r2 = &w1q[(k4 * 4 + 2) * 8];
        const ulonglong2* r3 = &w1q[(k4 * 4 + 3) * 8];
#pragma unroll
        for (int q = 0; q < 8; q++) {
            ulonglong2 w;
            w = r0[q]; fma2(acc[2 * q], a0, w.x, acc[2 * q]); fma2(acc[2 * q + 1], a0, w.y, acc[2 * q + 1]);
            w = r1[q]; fma2(acc[2 * q], a1, w.x, acc[2 * q]); fma2(acc[2 * q + 1], a1, w.y, acc[2 * q + 1]);
            w = r2[q]; fma2(acc[2 * q], a2, w.x, acc[2 * q]); fma2(acc[2 * q + 1], a2, w.y, acc[2 * q + 1]);
            w = r3[q]; fma2(acc[2 * q], a3, w.x, acc[2 * q]); fma2(acc[2 * q + 1], a3, w.y, acc[2 * q + 1]);
        }
    }

    float h1[32];
#pragma unroll
    for (int p = 0; p < 16; p++) {
        float lo, hi;
        unpack2(acc[p], lo, hi);
        h1[2 * p]     = fmaxf(lo, 0.0f);
        h1[2 * p + 1] = fmaxf(hi, 0.0f);
    }

    // ---- layer 2: 32 -> 16 (packed; weights via LDS.128) ----
    uint64_t acc2[8];
#pragma unroll
    for (int p = 0; p < 8; p++) acc2[p] = pack2(sb2[2 * p], sb2[2 * p + 1]);
    const ulonglong2* w2q = reinterpret_cast<const ulonglong2*>(sW2); // [32][4]
#pragma unroll
    for (int k = 0; k < 32; k++) {
        uint64_t a = dup2(h1[k]);
        const ulonglong2* wr = &w2q[k * 4];
#pragma unroll
        for (int q = 0; q < 4; q++) {
            ulonglong2 w = wr[q];
            fma2(acc2[2 * q],     a, w.x, acc2[2 * q]);
            fma2(acc2[2 * q + 1], a, w.y, acc2[2 * q + 1]);
        }
    }

    float h2[16];
#pragma unroll
    for (int p = 0; p < 8; p++) {
        float lo, hi;
        unpack2(acc2[p], lo, hi);
        h2[2 * p]     = fmaxf(lo, 0.0f);
        h2[2 * p + 1] = fmaxf(hi, 0.0f);
    }

    // ---- layer 3: 16 -> 3 (scalar) ----
    float o0 = sb3[0], o1 = sb3[1], o2 = sb3[2];
#pragma unroll
    for (int k = 0; k < 16; k++) {
        float a = h2[k];
        o0 = fmaf(a, sW3[k * 3 + 0], o0);
        o1 = fmaf(a, sW3[k * 3 + 1], o1);
        o2 = fmaf(a, sW3[k * 3 + 2], o2);
    }

    float m = (mask[i] != 0) ? 1.0f : 0.0f;
    o0 *= m; o1 *= m; o2 *= m;

    out[(size_t)3 * i + 0] = o0;
    out[(size_t)3 * i + 1] = o1;
    out[(size_t)3 * i + 2] = o2;

    // new_coords = coords with cols 1:4 += round(offsets)  (round-half-even)
    int4 c = reinterpret_cast<const int4*>(coords)[i];
    int n1 = c.y + (int)rintf(o0);
    int n2 = c.z + (int)rintf(o1);
    int n3 = c.w + (int)rintf(o2);

    reinterpret_cast<int4*>(g_newc)[i] = make_int4(c.x, n1, n2, n3);

    // 47-bit lexicographic key: c.x (11b) | 3 x 12-bit biased fields
    uint64_t key = ((uint64_t)(uint32_t)c.x          << 36)
                 | ((uint64_t)(uint32_t)(n1 + 1024)  << 24)
                 | ((uint64_t)(uint32_t)(n2 + 1024)  << 12)
                 |  (uint64_t)(uint32_t)(n3 + 1024);
    g_keys[i] = key;

    // bucket histogram (top 16 bits); g_hist reset by scan kernel each call
    atomicAdd(&g_hist[(uint32_t)(key >> 31)], 1u);

    // zero out_coords region (rows beyond num_unique must stay 0)
    reinterpret_cast<float4*>(out + (size_t)3 * n)[i] = make_float4(0.f, 0.f, 0.f, 0.f);
}

// ---------------------------------------------------------------------------
// Single-block exclusive scan over 65536 counters (1024 thr x 64 each).
// outA gets exclusive prefix (+ total at [NBUCKETS]); outB optional copy.
// reset!=0 zeroes the input after reading (graph-replay determinism).
// ---------------------------------------------------------------------------
__global__ void __launch_bounds__(1024)
scan64k_kernel(uint32_t* __restrict__ in, uint32_t* __restrict__ outA,
               uint32_t* __restrict__ outB, int reset)
{
    __shared__ uint32_t part[1024];
    int t = threadIdx.x;
    int base = t * 64;

    uint32_t s = 0;
    const uint4* in4 = reinterpret_cast<const uint4*>(in + base);
#pragma unroll
    for (int k = 0; k < 16; k++) {
        uint4 x = in4[k];
        s += x.x + x.y + x.z + x.w;
    }
    part[t] = s;
    __syncthreads();
#pragma unroll
    for (int d = 1; d < 1024; d <<= 1) {
        uint32_t x = (t >= d) ? part[t - d] : 0u;
        __syncthreads();
        part[t] += x;
        __syncthreads();
    }
    uint32_t excl = part[t] - s;
    for (int k = 0; k < 64; k++) {
        uint32_t v = in[base + k];
        outA[base + k] = excl;
        if (outB) outB[base + k] = excl;
        excl += v;
        if (reset) in[base + k] = 0u;
    }
    if (t == 1023) outA[NBUCKETS] = excl;   // total (== n for hist scan)
}

// ---------------------------------------------------------------------------
// Kernel 3: distribute (key, idx) into buckets
// ---------------------------------------------------------------------------
__global__ void distribute_kernel(int n)
{
    int i = blockIdx.x * blockDim.x + threadIdx.x;
    if (i >= n) return;
    uint64_t k = g_keys[i];
    uint32_t b = (uint32_t)(k >> 31);
    uint32_t pos = atomicAdd(&g_cursor[b], 1u);
    g_bkeys[pos] = k;
    g_bvals[pos] = (uint32_t)i;
}

// ---------------------------------------------------------------------------
// Kernel 4: per-bucket (one warp each) first-occurrence flags + unique count
// ---------------------------------------------------------------------------
__global__ void __launch_bounds__(WPB * 32)
uniq_kernel(void)
{
    __shared__ uint64_t sk[WPB][CAP];

    int warp = threadIdx.x >> 5;
    int lane = threadIdx.x & 31;
    int b = blockIdx.x * WPB + warp;

    uint32_t start = g_off[b];
    int cnt = (int)(g_off[b + 1] - start);
    if (cnt == 0) { if (lane == 0) g_uniq[b] = 0; return; }
    if (cnt > CAP) cnt = CAP;   // unreachable statistically; keeps memory safe

    uint64_t* k = sk[warp];
    for (int p = lane; p < cnt; p += 32) k[p] = g_bkeys[start + p];
    __syncwarp();

    uint32_t u = 0;
    for (int p = lane; p < cnt; p += 32) {
        uint64_t key = k[p];
        bool first = true;
        for (int j = 0; j < p; j++)
            if (k[j] == key) { first = false; break; }
        u += first ? 1u : 0u;
        g_bkeys[start + p] = key | (first ? FIRSTBIT : 0ull);
    }
#pragma unroll
    for (int d = 16; d > 0; d >>= 1)
        u += __shfl_down_sync(0xFFFFFFFFu, u, d);
    if (lane == 0) g_uniq[b] = u;
}

// ---------------------------------------------------------------------------
// Kernel 5: per-bucket (one warp each) rank + inverse map + segment means
// ---------------------------------------------------------------------------
__global__ void __launch_bounds__(WPB * 32)
finalize_kernel(float* __restrict__ out, int n)
{
    __shared__ uint64_t sk[WPB][CAP];    // with first-bit in bit 63
    __shared__ uint32_t sv[WPB][CAP];

    int warp = threadIdx.x >> 5;
    int lane = threadIdx.x & 31;
    int b = blockIdx.x * WPB + warp;

    uint32_t start = g_off[b];
    int cnt = (int)(g_off[b + 1] - start);
    if (cnt == 0) return;
    if (cnt > CAP) cnt = CAP;

    uint64_t* k = sk[warp];
    uint32_t* v = sv[warp];
    for (int p = lane; p < cnt; p += 32) {
        k[p] = g_bkeys[start + p];
        v[p] = g_bvals[start + p];
    }
    __syncwarp();

    uint32_t base = g_ubase[b];
    const int4* ncp = reinterpret_cast<const int4*>(g_newc);

    for (int p = lane; p < cnt; p += 32) {
        uint64_t kp = k[p];
        uint64_t myk = kp & KEYMASK;
        bool first = (kp & FIRSTBIT) != 0ull;

        uint32_t less = 0;
        float sx = 0.f, sy = 0.f, sz = 0.f, sw = 0.f;
        int ecnt = 0;
        for (int j = 0; j < cnt; j++) {
            uint64_t kj = k[j];
            uint64_t kjm = kj & KEYMASK;
            less += (uint32_t)((kjm < myk) & (kj >> 63));
            if (first && kjm == myk) {       // usually only j == p
                int4 m2 = ncp[v[j]];
                sx += (float)m2.x; sy += (float)m2.y;
                sz += (float)m2.z; sw += (float)m2.w;
                ecnt++;
            }
        }
        uint32_t r = base + less;

        // inv map (float32) at offset 7n
        out[(size_t)7 * n + v[p]] = (float)r;

        if (first) {
            float c = (float)ecnt;
            float* oc = out + (size_t)3 * n + (size_t)4 * r;
            // matches jax: f32 divide then astype(int32) (trunc toward zero)
            oc[0] = (float)(int)(sx / c);
            oc[1] = (float)(int)(sy / c);
            oc[2] = (float)(int)(sz / c);
            oc[3] = (float)(int)(sw / c);
        }
    }
}

// ---------------------------------------------------------------------------
// Host launch
// ---------------------------------------------------------------------------
extern "C" void kernel_launch(void* const* d_in, const int* in_sizes, int n_in,
                              void* d_out, int out_size)
{
    const float* feats  = (const float*)d_in[0];
    const int*   coords = (const int*)d_in[1];
    const int*   mask   = (const int*)d_in[2];
    const float* W1 = (const float*)d_in[3];
    const float* b1 = (const float*)d_in[4];
    const float* W2 = (const float*)d_in[5];
    const float* b2 = (const float*)d_in[6];
    const float* W3 = (const float*)d_in[7];
    const float* b3 = (const float*)d_in[8];
    float* out = (float*)d_out;

    int n = in_sizes[0] / 64;
    if (n > NMAX) n = NMAX;

    void *p_hist, *p_off, *p_cursor, *p_uniq, *p_ubase;
    cudaGetSymbolAddress(&p_hist,   g_hist);
    cudaGetSymbolAddress(&p_off,    g_off);
    cudaGetSymbolAddress(&p_cursor, g_cursor);
    cudaGetSymbolAddress(&p_uniq,   g_uniq);
    cudaGetSymbolAddress(&p_ubase,  g_ubase);

    const int BLK = 256;
    int grid = (n + BLK - 1) / BLK;

    // 1) decode + keys + bucket histogram + out_coords zero
    decode_kernel<<<grid, BLK>>>(feats, coords, mask, W1, b1, W2, b2, W3, b3, out, n);

    // 2) bucket offsets + cursors (and hist reset for replay determinism)
    scan64k_kernel<<<1, 1024>>>((uint32_t*)p_hist, (uint32_t*)p_off,
                                (uint32_t*)p_cursor, 1);

    // 3) distribute into buckets
    distribute_kernel<<<grid, BLK>>>(n);

    // 4) per-bucket first-occurrence flags + unique counts (1 warp / bucket)
    uniq_kernel<<<NBUCKETS / WPB, WPB * 32>>>();

    // 5) exclusive scan of unique counts -> global rank bases
    scan64k_kernel<<<1, 1024>>>((uint32_t*)p_uniq, (uint32_t*)p_ubase,
                                nullptr, 0);

    // 6) ranks + inverse map + segment means (1 warp / bucket)
    finalize_kernel<<<NBUCKETS / WPB, WPB * 32>>>(out, n);
}

// round 7
// speedup vs baseline: 1.9126x; 1.9126x over previous
#include <cuda_runtime.h>
#include <cuda_bf16.h>
#include <cub/cub.cuh>
#include <cstdint>

#define NMAX 1000000
#define NBUCKETS 65536            // top 16 bits of the 47-bit key (bits 31..46)
#define CAP 128                   // max bucket size (lambda ~15-30; 128 is >>17 sigma)
#define WPB 8                     // warps per block in bucket kernels

// ---------------------------------------------------------------------------
// Static device scratch (no allocations allowed anywhere)
// ---------------------------------------------------------------------------
__device__ uint64_t g_keys[NMAX];        // decode output (unordered)
__device__ uint64_t g_bkeys[NMAX];       // bucket-distributed keys (+first bit)
__device__ uint32_t g_bvals[NMAX];       // bucket-distributed original indices
__device__ int      g_newc[(size_t)NMAX * 4];
__device__ uint32_t g_hist[NBUCKETS];    // zero-init; reset by copyreset each call
__device__ uint32_t g_off[NBUCKETS + 1];
__device__ uint32_t g_cursor[NBUCKETS];
__device__ uint32_t g_uniq[NBUCKETS];
__device__ uint32_t g_ubase[NBUCKETS];
__device__ unsigned char g_temp[4u * 1024u * 1024u];

#define KEYMASK ((1ull << 47) - 1ull)
#define FIRSTBIT (1ull << 63)

// ---------------------------------------------------------------------------
// Packed f32x2 helpers (FFMA2 — PTX-only on sm_103a)
// ---------------------------------------------------------------------------
__device__ __forceinline__ void fma2(uint64_t& d, uint64_t a, uint64_t b, uint64_t c) {
    asm("fma.rn.f32x2 %0, %1, %2, %3;" : "=l"(d) : "l"(a), "l"(b), "l"(c));
}
__device__ __forceinline__ uint64_t dup2(float x) {
    uint64_t r; uint32_t u = __float_as_uint(x);
    asm("mov.b64 %0, {%1, %1};" : "=l"(r) : "r"(u));
    return r;
}
__device__ __forceinline__ uint64_t pack2(float lo, float hi) {
    uint64_t r;
    asm("mov.b64 %0, {%1, %2};" : "=l"(r) : "r"(__float_as_uint(lo)), "r"(__float_as_uint(hi)));
    return r;
}
__device__ __forceinline__ void unpack2(uint64_t v, float& lo, float& hi) {
    uint32_t a, b;
    asm("mov.b64 {%0, %1}, %2;" : "=r"(a), "=r"(b) : "l"(v));
    lo = __uint_as_float(a); hi = __uint_as_float(b);
}

// ---------------------------------------------------------------------------
// Kernel 1: MLP decode (f32x2, LDS.128 weight loads) + key + histogram + zero
// ---------------------------------------------------------------------------
__global__ void __launch_bounds__(256)
decode_kernel(const float* __restrict__ feats,
              const int*   __restrict__ coords,
              const int*   __restrict__ mask,
              const float* __restrict__ W1, const float* __restrict__ b1,
              const float* __restrict__ W2, const float* __restrict__ b2,
              const float* __restrict__ W3, const float* __restrict__ b3,
              float* __restrict__ out, int n)
{
    __shared__ __align__(16) float sW1[64 * 32];
    __shared__ __align__(16) float sW2[32 * 16];
    __shared__ __align__(16) float sW3[16 * 3];
    __shared__ __align__(16) float sb1[32];
    __shared__ __align__(16) float sb2[16];
    __shared__ __align__(16) float sb3[4];

    for (int t = threadIdx.x; t < 64 * 32; t += blockDim.x) sW1[t] = W1[t];
    for (int t = threadIdx.x; t < 32 * 16; t += blockDim.x) sW2[t] = W2[t];
    for (int t = threadIdx.x; t < 16 * 3;  t += blockDim.x) sW3[t] = W3[t];
    if (threadIdx.x < 32) sb1[threadIdx.x] = b1[threadIdx.x];
    if (threadIdx.x < 16) sb2[threadIdx.x] = b2[threadIdx.x];
    if (threadIdx.x < 3)  sb3[threadIdx.x] = b3[threadIdx.x];
    __syncthreads();

    int i = blockIdx.x * blockDim.x + threadIdx.x;
    if (i >= n) return;

    // ---- layer 1: 64 -> 32 (packed pairs; weights via LDS.128) ----
    uint64_t acc[16];
#pragma unroll
    for (int p = 0; p < 16; p++) acc[p] = pack2(sb1[2 * p], sb1[2 * p + 1]);

    const ulonglong2* w1q = reinterpret_cast<const ulonglong2*>(sW1); // [64][8]
    const float4* f4 = reinterpret_cast<const float4*>(feats) + (size_t)i * 16;
#pragma unroll
    for (int k4 = 0; k4 < 16; k4++) {
        float4 f = f4[k4];
        uint64_t a0 = dup2(f.x), a1 = dup2(f.y), a2 = dup2(f.z), a3 = dup2(f.w);
        const ulonglong2* r0 = &w1q[(k4 * 4 + 0) * 8];
        const ulonglong2* r1 = &w1q[(k4 * 4 + 1) * 8];
        const ulonglong2* r2 = &w1q[(k4 * 4 + 2) * 8];
        const ulonglong2* r3 = &w1q[(k4 * 4 + 3) * 8];
#pragma unroll
        for (int q = 0; q < 8; q++) {
            ulonglong2 w;
            w = r0[q]; fma2(acc[2 * q], a0, w.x, acc[2 * q]); fma2(acc[2 * q + 1], a0, w.y, acc[2 * q + 1]);
            w = r1[q]; fma2(acc[2 * q], a1, w.x, acc[2 * q]); fma2(acc[2 * q + 1], a1, w.y, acc[2 * q + 1]);
            w = r2[q]; fma2(acc[2 * q], a2, w.x, acc[2 * q]); fma2(acc[2 * q + 1], a2, w.y, acc[2 * q + 1]);
            w = r3[q]; fma2(acc[2 * q], a3, w.x, acc[2 * q]); fma2(acc[2 * q + 1], a3, w.y, acc[2 * q + 1]);
        }
    }

    float h1[32];
#pragma unroll
    for (int p = 0; p < 16; p++) {
        float lo, hi;
        unpack2(acc[p], lo, hi);
        h1[2 * p]     = fmaxf(lo, 0.0f);
        h1[2 * p + 1] = fmaxf(hi, 0.0f);
    }

    // ---- layer 2: 32 -> 16 (packed; weights via LDS.128) ----
    uint64_t acc2[8];
#pragma unroll
    for (int p = 0; p < 8; p++) acc2[p] = pack2(sb2[2 * p], sb2[2 * p + 1]);
    const ulonglong2* w2q = reinterpret_cast<const ulonglong2*>(sW2); // [32][4]
#pragma unroll
    for (int k = 0; k < 32; k++) {
        uint64_t a = dup2(h1[k]);
        const ulonglong2* wr = &w2q[k * 4];
#pragma unroll
        for (int q = 0; q < 4; q++) {
            ulonglong2 w = wr[q];
            fma2(acc2[2 * q],     a, w.x, acc2[2 * q]);
            fma2(acc2[2 * q + 1], a, w.y, acc2[2 * q + 1]);
        }
    }

    float h2[16];
#pragma unroll
    for (int p = 0; p < 8; p++) {
        float lo, hi;
        unpack2(acc2[p], lo, hi);
        h2[2 * p]     = fmaxf(lo, 0.0f);
        h2[2 * p + 1] = fmaxf(hi, 0.0f);
    }

    // ---- layer 3: 16 -> 3 (scalar) ----
    float o0 = sb3[0], o1 = sb3[1], o2 = sb3[2];
#pragma unroll
    for (int k = 0; k < 16; k++) {
        float a = h2[k];
        o0 = fmaf(a, sW3[k * 3 + 0], o0);
        o1 = fmaf(a, sW3[k * 3 + 1], o1);
        o2 = fmaf(a, sW3[k * 3 + 2], o2);
    }

    float m = (mask[i] != 0) ? 1.0f : 0.0f;
    o0 *= m; o1 *= m; o2 *= m;

    out[(size_t)3 * i + 0] = o0;
    out[(size_t)3 * i + 1] = o1;
    out[(size_t)3 * i + 2] = o2;

    // new_coords = coords with cols 1:4 += round(offsets)  (round-half-even)
    int4 c = reinterpret_cast<const int4*>(coords)[i];
    int n1 = c.y + (int)rintf(o0);
    int n2 = c.z + (int)rintf(o1);
    int n3 = c.w + (int)rintf(o2);

    reinterpret_cast<int4*>(g_newc)[i] = make_int4(c.x, n1, n2, n3);

    // 47-bit lexicographic key: c.x (11b) | 3 x 12-bit biased fields
    uint64_t key = ((uint64_t)(uint32_t)c.x          << 36)
                 | ((uint64_t)(uint32_t)(n1 + 1024)  << 24)
                 | ((uint64_t)(uint32_t)(n2 + 1024)  << 12)
                 |  (uint64_t)(uint32_t)(n3 + 1024);
    g_keys[i] = key;

    // bucket histogram (top 16 bits); reset by copyreset_kernel each call
    atomicAdd(&g_hist[(uint32_t)(key >> 31)], 1u);

    // zero out_coords region (rows beyond num_unique must stay 0)
    reinterpret_cast<float4*>(out + (size_t)3 * n)[i] = make_float4(0.f, 0.f, 0.f, 0.f);
}

// ---------------------------------------------------------------------------
// Kernel 2b: cursor init + hist reset + sentinel (parallel, after cub scan)
// ---------------------------------------------------------------------------
__global__ void copyreset_kernel(int n)
{
    int i = blockIdx.x * blockDim.x + threadIdx.x;
    if (i >= NBUCKETS) return;
    g_cursor[i] = g_off[i];
    g_hist[i] = 0u;                       // replay determinism
    if (i == 0) g_off[NBUCKETS] = (uint32_t)n;
}

// ---------------------------------------------------------------------------
// Kernel 3: distribute (key, idx) into buckets
// ---------------------------------------------------------------------------
__global__ void distribute_kernel(int n)
{
    int i = blockIdx.x * blockDim.x + threadIdx.x;
    if (i >= n) return;
    uint64_t k = g_keys[i];
    uint32_t b = (uint32_t)(k >> 31);
    uint32_t pos = atomicAdd(&g_cursor[b], 1u);
    g_bkeys[pos] = k;
    g_bvals[pos] = (uint32_t)i;
}

// ---------------------------------------------------------------------------
// Kernel 4: per-bucket (one warp each) first-occurrence flags + unique count
// ---------------------------------------------------------------------------
__global__ void __launch_bounds__(WPB * 32)
uniq_kernel(void)
{
    __shared__ uint64_t sk[WPB][CAP];

    int warp = threadIdx.x >> 5;
    int lane = threadIdx.x & 31;
    int b = blockIdx.x * WPB + warp;

    uint32_t start = g_off[b];
    int cnt = (int)(g_off[b + 1] - start);
    if (cnt == 0) { if (lane == 0) g_uniq[b] = 0; return; }
    if (cnt > CAP) cnt = CAP;   // unreachable statistically; keeps memory safe

    uint64_t* k = sk[warp];
    for (int p = lane; p < cnt; p += 32) k[p] = g_bkeys[start + p];
    __syncwarp();

    uint32_t u = 0;
    for (int p = lane; p < cnt; p += 32) {
        uint64_t key = k[p];
        bool first = true;
        for (int j = 0; j < p; j++)
            if (k[j] == key) { first = false; break; }
        u += first ? 1u : 0u;
        g_bkeys[start + p] = key | (first ? FIRSTBIT : 0ull);
    }
#pragma unroll
    for (int d = 16; d > 0; d >>= 1)
        u += __shfl_down_sync(0xFFFFFFFFu, u, d);
    if (lane == 0) g_uniq[b] = u;
}

// ---------------------------------------------------------------------------
// Kernel 5: per-bucket (one warp each) rank + inverse map + segment means
// ---------------------------------------------------------------------------
__global__ void __launch_bounds__(WPB * 32)
finalize_kernel(float* __restrict__ out, int n)
{
    __shared__ uint64_t sk[WPB][CAP];    // with first-bit in bit 63
    __shared__ uint32_t sv[WPB][CAP];

    int warp = threadIdx.x >> 5;
    int lane = threadIdx.x & 31;
    int b = blockIdx.x * WPB + warp;

    uint32_t start = g_off[b];
    int cnt = (int)(g_off[b + 1] - start);
    if (cnt == 0) return;
    if (cnt > CAP) cnt = CAP;

    uint64_t* k = sk[warp];
    uint32_t* v = sv[warp];
    for (int p = lane; p < cnt; p += 32) {
        k[p] = g_bkeys[start + p];
        v[p] = g_bvals[start + p];
    }
    __syncwarp();

    uint32_t base = g_ubase[b];
    const int4* ncp = reinterpret_cast<const int4*>(g_newc);

    for (int p = lane; p < cnt; p += 32) {
        uint64_t kp = k[p];
        uint64_t myk = kp & KEYMASK;
        bool first = (kp & FIRSTBIT) != 0ull;

        uint32_t less = 0;
        float sx = 0.f, sy = 0.f, sz = 0.f, sw = 0.f;
        int ecnt = 0;
        for (int j = 0; j < cnt; j++) {
            uint64_t kj = k[j];
            uint64_t kjm = kj & KEYMASK;
            less += (uint32_t)((kjm < myk) & (kj >> 63));
            if (first && kjm == myk) {       // usually only j == p
                int4 m2 = ncp[v[j]];
                sx += (float)m2.x; sy += (float)m2.y;
                sz += (float)m2.z; sw += (float)m2.w;
                ecnt++;
            }
        }
        uint32_t r = base + less;

        // inv map (float32) at offset 7n
        out[(size_t)7 * n + v[p]] = (float)r;

        if (first) {
            float c = (float)ecnt;
            float* oc = out + (size_t)3 * n + (size_t)4 * r;
            // matches jax: f32 divide then astype(int32) (trunc toward zero)
            oc[0] = (float)(int)(sx / c);
            oc[1] = (float)(int)(sy / c);
            oc[2] = (float)(int)(sz / c);
            oc[3] = (float)(int)(sw / c);
        }
    }
}

// ---------------------------------------------------------------------------
// Host launch
// ---------------------------------------------------------------------------
extern "C" void kernel_launch(void* const* d_in, const int* in_sizes, int n_in,
                              void* d_out, int out_size)
{
    const float* feats  = (const float*)d_in[0];
    const int*   coords = (const int*)d_in[1];
    const int*   mask   = (const int*)d_in[2];
    const float* W1 = (const float*)d_in[3];
    const float* b1 = (const float*)d_in[4];
    const float* W2 = (const float*)d_in[5];
    const float* b2 = (const float*)d_in[6];
    const float* W3 = (const float*)d_in[7];
    const float* b3 = (const float*)d_in[8];
    float* out = (float*)d_out;

    int n = in_sizes[0] / 64;
    if (n > NMAX) n = NMAX;

    void *p_hist, *p_off, *p_uniq, *p_ubase, *p_temp;
    cudaGetSymbolAddress(&p_hist,  g_hist);
    cudaGetSymbolAddress(&p_off,   g_off);
    cudaGetSymbolAddress(&p_uniq,  g_uniq);
    cudaGetSymbolAddress(&p_ubase, g_ubase);
    cudaGetSymbolAddress(&p_temp,  g_temp);

    const int BLK = 256;
    int grid = (n + BLK - 1) / BLK;

    // 1) decode + keys + bucket histogram + out_coords zero
    decode_kernel<<<grid, BLK>>>(feats, coords, mask, W1, b1, W2, b2, W3, b3, out, n);

    // 2) multi-block exclusive scan of histogram -> bucket offsets
    size_t tb = 0;
    cub::DeviceScan::ExclusiveSum(nullptr, tb, (const uint32_t*)p_hist,
                                  (uint32_t*)p_off, NBUCKETS, (cudaStream_t)0);
    if (tb > 4u * 1024u * 1024u) return;
    cub::DeviceScan::ExclusiveSum(p_temp, tb, (const uint32_t*)p_hist,
                                  (uint32_t*)p_off, NBUCKETS, (cudaStream_t)0);

    // 2b) cursor init + hist reset + off[NBUCKETS]=n
    copyreset_kernel<<<NBUCKETS / BLK, BLK>>>(n);

    // 3) distribute into buckets
    distribute_kernel<<<grid, BLK>>>(n);

    // 4) per-bucket first-occurrence flags + unique counts (1 warp / bucket)
    uniq_kernel<<<NBUCKETS / WPB, WPB * 32>>>();

    // 5) multi-block exclusive scan of unique counts -> global rank bases
    size_t tb2 = 0;
    cub::DeviceScan::ExclusiveSum(nullptr, tb2, (const uint32_t*)p_uniq,
                                  (uint32_t*)p_ubase, NBUCKETS, (cudaStream_t)0);
    if (tb2 > 4u * 1024u * 1024u) return;
    cub::DeviceScan::ExclusiveSum(p_temp, tb2, (const uint32_t*)p_uniq,
                                  (uint32_t*)p_ubase, NBUCKETS, (cudaStream_t)0);

    // 6) ranks + inverse map + segment means (1 warp / bucket)
    finalize_kernel<<<NBUCKETS / WPB, WPB * 32>>>(out, n);
}

// round 8
// speedup vs baseline: 2.3389x; 1.2229x over previous
#include <cuda_runtime.h>
#include <cuda_bf16.h>
#include <cub/cub.cuh>
#include <cstdint>

#define NMAX 1000000
#define NBUCKETS 65536            // top 16 bits of the 47-bit key (bits 31..46)
#define CAP 128                   // max bucket size (lambda ~30; 128 is >>10 sigma)
#define WPB 8                     // warps per block in bucket kernels

// ---------------------------------------------------------------------------
// Static device scratch (no allocations allowed anywhere)
// ---------------------------------------------------------------------------
__device__ uint64_t g_keys[NMAX];        // decode output (unordered)
__device__ uint64_t g_bkeys[NMAX];       // bucket-distributed keys (+first bit)
__device__ uint32_t g_bvals[NMAX];       // bucket-distributed original indices
__device__ int      g_newc[(size_t)NMAX * 4];
__device__ uint32_t g_hist[NBUCKETS];    // zero-init; reset by copyreset each call
__device__ uint32_t g_off[NBUCKETS + 1];
__device__ uint32_t g_cursor[NBUCKETS];
__device__ uint32_t g_uniq[NBUCKETS];
__device__ uint32_t g_ubase[NBUCKETS];
__device__ unsigned char g_temp[4u * 1024u * 1024u];

#define KEYMASK ((1ull << 47) - 1ull)
#define FIRSTBIT (1ull << 63)

// ---------------------------------------------------------------------------
// Packed f32x2 helpers (FFMA2 — PTX-only on sm_103a)
// ---------------------------------------------------------------------------
__device__ __forceinline__ void fma2(uint64_t& d, uint64_t a, uint64_t b, uint64_t c) {
    asm("fma.rn.f32x2 %0, %1, %2, %3;" : "=l"(d) : "l"(a), "l"(b), "l"(c));
}
__device__ __forceinline__ uint64_t dup2(float x) {
    uint64_t r; uint32_t u = __float_as_uint(x);
    asm("mov.b64 %0, {%1, %1};" : "=l"(r) : "r"(u));
    return r;
}
__device__ __forceinline__ uint64_t pack2(float lo, float hi) {
    uint64_t r;
    asm("mov.b64 %0, {%1, %2};" : "=l"(r) : "r"(__float_as_uint(lo)), "r"(__float_as_uint(hi)));
    return r;
}
__device__ __forceinline__ void unpack2(uint64_t v, float& lo, float& hi) {
    uint32_t a, b;
    asm("mov.b64 {%0, %1}, %2;" : "=r"(a), "=r"(b) : "l"(v));
    lo = __uint_as_float(a); hi = __uint_as_float(b);
}

// ---------------------------------------------------------------------------
// Kernel 1: MLP decode, TWO points per thread (i and i + n/2).
// Weight LDS.128 loads are shared between both points' FMA2 streams.
// ---------------------------------------------------------------------------
__global__ void __launch_bounds__(256)
decode_kernel(const float* __restrict__ feats,
              const int*   __restrict__ coords,
              const int*   __restrict__ mask,
              const float* __restrict__ W1, const float* __restrict__ b1,
              const float* __restrict__ W2, const float* __restrict__ b2,
              const float* __restrict__ W3, const float* __restrict__ b3,
              float* __restrict__ out, int n)
{
    __shared__ __align__(16) float sW1[64 * 32];
    __shared__ __align__(16) float sW2[32 * 16];
    __shared__ __align__(16) float sW3[16 * 3];
    __shared__ __align__(16) float sb1[32];
    __shared__ __align__(16) float sb2[16];
    __shared__ __align__(16) float sb3[4];

    for (int t = threadIdx.x; t < 64 * 32; t += blockDim.x) sW1[t] = W1[t];
    for (int t = threadIdx.x; t < 32 * 16; t += blockDim.x) sW2[t] = W2[t];
    for (int t = threadIdx.x; t < 16 * 3;  t += blockDim.x) sW3[t] = W3[t];
    if (threadIdx.x < 32) sb1[threadIdx.x] = b1[threadIdx.x];
    if (threadIdx.x < 16) sb2[threadIdx.x] = b2[threadIdx.x];
    if (threadIdx.x < 3)  sb3[threadIdx.x] = b3[threadIdx.x];
    __syncthreads();

    int nhalf = (n + 1) >> 1;
    int i = blockIdx.x * blockDim.x + threadIdx.x;
    if (i >= nhalf) return;
    int iA = i;
    int iB = i + nhalf;
    bool hasB = (iB < n);
    int iBs = hasB ? iB : iA;            // safe source for B-lane loads

    // ---- layer 1: 64 -> 32, two points, shared weight loads ----
    uint64_t accA[16], accB[16];
#pragma unroll
    for (int p = 0; p < 16; p++) {
        uint64_t b = pack2(sb1[2 * p], sb1[2 * p + 1]);
        accA[p] = b; accB[p] = b;
    }

    const ulonglong2* w1q = reinterpret_cast<const ulonglong2*>(sW1); // [64][8]
    const float4* fA = reinterpret_cast<const float4*>(feats) + (size_t)iA * 16;
    const float4* fB = reinterpret_cast<const float4*>(feats) + (size_t)iBs * 16;
#pragma unroll
    for (int k4 = 0; k4 < 16; k4++) {
        float4 fa = fA[k4];
        float4 fb = fB[k4];
        uint64_t a0 = dup2(fa.x), a1 = dup2(fa.y), a2 = dup2(fa.z), a3 = dup2(fa.w);
        uint64_t e0 = dup2(fb.x), e1 = dup2(fb.y), e2 = dup2(fb.z), e3 = dup2(fb.w);
        const ulonglong2* r0 = &w1q[(k4 * 4 + 0) * 8];
        const ulonglong2* r1 = &w1q[(k4 * 4 + 1) * 8];
        const ulonglong2* r2 = &w1q[(k4 * 4 + 2) * 8];
        const ulonglong2* r3 = &w1q[(k4 * 4 + 3) * 8];
#pragma unroll
        for (int q = 0; q < 8; q++) {
            ulonglong2 w;
            w = r0[q];
            fma2(accA[2*q], a0, w.x, accA[2*q]); fma2(accA[2*q+1], a0, w.y, accA[2*q+1]);
            fma2(accB[2*q], e0, w.x, accB[2*q]); fma2(accB[2*q+1], e0, w.y, accB[2*q+1]);
            w = r1[q];
            fma2(accA[2*q], a1, w.x, accA[2*q]); fma2(accA[2*q+1], a1, w.y, accA[2*q+1]);
            fma2(accB[2*q], e1, w.x, accB[2*q]); fma2(accB[2*q+1], e1, w.y, accB[2*q+1]);
            w = r2[q];
            fma2(accA[2*q], a2, w.x, accA[2*q]); fma2(accA[2*q+1], a2, w.y, accA[2*q+1]);
            fma2(accB[2*q], e2, w.x, accB[2*q]); fma2(accB[2*q+1], e2, w.y, accB[2*q+1]);
            w = r3[q];
            fma2(accA[2*q], a3, w.x, accA[2*q]); fma2(accA[2*q+1], a3, w.y, accA[2*q+1]);
            fma2(accB[2*q], e3, w.x, accB[2*q]); fma2(accB[2*q+1], e3, w.y, accB[2*q+1]);
        }
    }

    float h1A[32], h1B[32];
#pragma unroll
    for (int p = 0; p < 16; p++) {
        float lo, hi;
        unpack2(accA[p], lo, hi);
        h1A[2*p] = fmaxf(lo, 0.0f); h1A[2*p+1] = fmaxf(hi, 0.0f);
        unpack2(accB[p], lo, hi);
        h1B[2*p] = fmaxf(lo, 0.0f); h1B[2*p+1] = fmaxf(hi, 0.0f);
    }

    // ---- layer 2: 32 -> 16, two points, shared weight loads ----
    uint64_t ac2A[8], ac2B[8];
#pragma unroll
    for (int p = 0; p < 8; p++) {
        uint64_t b = pack2(sb2[2 * p], sb2[2 * p + 1]);
        ac2A[p] = b; ac2B[p] = b;
    }
    const ulonglong2* w2q = reinterpret_cast<const ulonglong2*>(sW2); // [32][4]
#pragma unroll
    for (int k = 0; k < 32; k++) {
        uint64_t a = dup2(h1A[k]);
        uint64_t e = dup2(h1B[k]);
        const ulonglong2* wr = &w2q[k * 4];
#pragma unroll
        for (int q = 0; q < 4; q++) {
            ulonglong2 w = wr[q];
            fma2(ac2A[2*q],   a, w.x, ac2A[2*q]);   fma2(ac2A[2*q+1], a, w.y, ac2A[2*q+1]);
            fma2(ac2B[2*q],   e, w.x, ac2B[2*q]);   fma2(ac2B[2*q+1], e, w.y, ac2B[2*q+1]);
        }
    }

    float h2A[16], h2B[16];
#pragma unroll
    for (int p = 0; p < 8; p++) {
        float lo, hi;
        unpack2(ac2A[p], lo, hi);
        h2A[2*p] = fmaxf(lo, 0.0f); h2A[2*p+1] = fmaxf(hi, 0.0f);
        unpack2(ac2B[p], lo, hi);
        h2B[2*p] = fmaxf(lo, 0.0f); h2B[2*p+1] = fmaxf(hi, 0.0f);
    }

    // ---- layer 3: 16 -> 3, two points ----
    float oA0 = sb3[0], oA1 = sb3[1], oA2 = sb3[2];
    float oB0 = sb3[0], oB1 = sb3[1], oB2 = sb3[2];
#pragma unroll
    for (int k = 0; k < 16; k++) {
        float w0 = sW3[k * 3 + 0], w1 = sW3[k * 3 + 1], w2 = sW3[k * 3 + 2];
        oA0 = fmaf(h2A[k], w0, oA0); oA1 = fmaf(h2A[k], w1, oA1); oA2 = fmaf(h2A[k], w2, oA2);
        oB0 = fmaf(h2B[k], w0, oB0); oB1 = fmaf(h2B[k], w1, oB1); oB2 = fmaf(h2B[k], w2, oB2);
    }

    // ---- epilogue per point ----
    {
        float m = (mask[iA] != 0) ? 1.0f : 0.0f;
        float o0 = oA0 * m, o1 = oA1 * m, o2 = oA2 * m;
        out[(size_t)3 * iA + 0] = o0;
        out[(size_t)3 * iA + 1] = o1;
        out[(size_t)3 * iA + 2] = o2;
        int4 c = reinterpret_cast<const int4*>(coords)[iA];
        int n1 = c.y + (int)rintf(o0);
        int n2 = c.z + (int)rintf(o1);
        int n3 = c.w + (int)rintf(o2);
        reinterpret_cast<int4*>(g_newc)[iA] = make_int4(c.x, n1, n2, n3);
        uint64_t key = ((uint64_t)(uint32_t)c.x         << 36)
                     | ((uint64_t)(uint32_t)(n1 + 1024) << 24)
                     | ((uint64_t)(uint32_t)(n2 + 1024) << 12)
                     |  (uint64_t)(uint32_t)(n3 + 1024);
        g_keys[iA] = key;
        atomicAdd(&g_hist[(uint32_t)(key >> 31)], 1u);
        reinterpret_cast<float4*>(out + (size_t)3 * n)[iA] = make_float4(0.f, 0.f, 0.f, 0.f);
    }
    if (hasB) {
        float m = (mask[iB] != 0) ? 1.0f : 0.0f;
        float o0 = oB0 * m, o1 = oB1 * m, o2 = oB2 * m;
        out[(size_t)3 * iB + 0] = o0;
        out[(size_t)3 * iB + 1] = o1;
        out[(size_t)3 * iB + 2] = o2;
        int4 c = reinterpret_cast<const int4*>(coords)[iB];
        int n1 = c.y + (int)rintf(o0);
        int n2 = c.z + (int)rintf(o1);
        int n3 = c.w + (int)rintf(o2);
        reinterpret_cast<int4*>(g_newc)[iB] = make_int4(c.x, n1, n2, n3);
        uint64_t key = ((uint64_t)(uint32_t)c.x         << 36)
                     | ((uint64_t)(uint32_t)(n1 + 1024) << 24)
                     | ((uint64_t)(uint32_t)(n2 + 1024) << 12)
                     |  (uint64_t)(uint32_t)(n3 + 1024);
        g_keys[iB] = key;
        atomicAdd(&g_hist[(uint32_t)(key >> 31)], 1u);
        reinterpret_cast<float4*>(out + (size_t)3 * n)[iB] = make_float4(0.f, 0.f, 0.f, 0.f);
    }
}

// ---------------------------------------------------------------------------
// Kernel 2b: cursor init + hist reset + sentinel (parallel, after cub scan)
// ---------------------------------------------------------------------------
__global__ void copyreset_kernel(int n)
{
    int i = blockIdx.x * blockDim.x + threadIdx.x;
    if (i >= NBUCKETS) return;
    g_cursor[i] = g_off[i];
    g_hist[i] = 0u;                       // replay determinism
    if (i == 0) g_off[NBUCKETS] = (uint32_t)n;
}

// ---------------------------------------------------------------------------
// Kernel 3: distribute (key, idx) into buckets
// ---------------------------------------------------------------------------
__global__ void distribute_kernel(int n)
{
    int i = blockIdx.x * blockDim.x + threadIdx.x;
    if (i >= n) return;
    uint64_t k = g_keys[i];
    uint32_t b = (uint32_t)(k >> 31);
    uint32_t pos = atomicAdd(&g_cursor[b], 1u);
    g_bkeys[pos] = k;
    g_bvals[pos] = (uint32_t)i;
}

// ---------------------------------------------------------------------------
// Kernel 4: per-bucket (one warp each) first-occurrence flags + unique count
// ---------------------------------------------------------------------------
__global__ void __launch_bounds__(WPB * 32)
uniq_kernel(void)
{
    __shared__ uint64_t sk[WPB][CAP];

    int warp = threadIdx.x >> 5;
    int lane = threadIdx.x & 31;
    int b = blockIdx.x * WPB + warp;

    uint32_t start = g_off[b];
    int cnt = (int)(g_off[b + 1] - start);
    if (cnt == 0) { if (lane == 0) g_uniq[b] = 0; return; }
    if (cnt > CAP) cnt = CAP;   // unreachable statistically; keeps memory safe

    uint64_t* k = sk[warp];
    for (int p = lane; p < cnt; p += 32) k[p] = g_bkeys[start + p];
    __syncwarp();

    uint32_t u = 0;
    for (int p = lane; p < cnt; p += 32) {
        uint64_t key = k[p];
        bool first = true;
        for (int j = 0; j < p; j++)
            if (k[j] == key) { first = false; break; }
        u += first ? 1u : 0u;
        g_bkeys[start + p] = key | (first ? FIRSTBIT : 0ull);
    }
#pragma unroll
    for (int d = 16; d > 0; d >>= 1)
        u += __shfl_down_sync(0xFFFFFFFFu, u, d);
    if (lane == 0) g_uniq[b] = u;
}

// ---------------------------------------------------------------------------
// Kernel 5: per-bucket (one warp each) rank + inverse map + segment means
// ---------------------------------------------------------------------------
__global__ void __launch_bounds__(WPB * 32)
finalize_kernel(float* __restrict__ out, int n)
{
    __shared__ uint64_t sk[WPB][CAP];    // with first-bit in bit 63
    __shared__ uint32_t sv[WPB][CAP];

    int warp = threadIdx.x >> 5;
    int lane = threadIdx.x & 31;
    int b = blockIdx.x * WPB + warp;

    uint32_t start = g_off[b];
    int cnt = (int)(g_off[b + 1] - start);
    if (cnt == 0) return;
    if (cnt > CAP) cnt = CAP;

    uint64_t* k = sk[warp];
    uint32_t* v = sv[warp];
    for (int p = lane; p < cnt; p += 32) {
        k[p] = g_bkeys[start + p];
        v[p] = g_bvals[start + p];
    }
    __syncwarp();

    uint32_t base = g_ubase[b];
    const int4* ncp = reinterpret_cast<const int4*>(g_newc);

    for (int p = lane; p < cnt; p += 32) {
        uint64_t kp = k[p];
        uint64_t myk = kp & KEYMASK;
        bool first = (kp & FIRSTBIT) != 0ull;

        uint32_t less = 0;
        float sx = 0.f, sy = 0.f, sz = 0.f, sw = 0.f;
        int ecnt = 0;
        for (int j = 0; j < cnt; j++) {
            uint64_t kj = k[j];
            uint64_t kjm = kj & KEYMASK;
            less += (uint32_t)((kjm < myk) & (kj >> 63));
            if (first && kjm == myk) {       // usually only j == p
                int4 m2 = ncp[v[j]];
                sx += (float)m2.x; sy += (float)m2.y;
                sz += (float)m2.z; sw += (float)m2.w;
                ecnt++;
            }
        }
        uint32_t r = base + less;

        // inv map (float32) at offset 7n
        out[(size_t)7 * n + v[p]] = (float)r;

        if (first) {
            float c = (float)ecnt;
            float* oc = out + (size_t)3 * n + (size_t)4 * r;
            // matches jax: f32 divide then astype(int32) (trunc toward zero)
            oc[0] = (float)(int)(sx / c);
            oc[1] = (float)(int)(sy / c);
            oc[2] = (float)(int)(sz / c);
            oc[3] = (float)(int)(sw / c);
        }
    }
}

// ---------------------------------------------------------------------------
// Host launch
// ---------------------------------------------------------------------------
extern "C" void kernel_launch(void* const* d_in, const int* in_sizes, int n_in,
                              void* d_out, int out_size)
{
    const float* feats  = (const float*)d_in[0];
    const int*   coords = (const int*)d_in[1];
    const int*   mask   = (const int*)d_in[2];
    const float* W1 = (const float*)d_in[3];
    const float* b1 = (const float*)d_in[4];
    const float* W2 = (const float*)d_in[5];
    const float* b2 = (const float*)d_in[6];
    const float* W3 = (const float*)d_in[7];
    const float* b3 = (const float*)d_in[8];
    float* out = (float*)d_out;

    int n = in_sizes[0] / 64;
    if (n > NMAX) n = NMAX;

    void *p_hist, *p_off, *p_uniq, *p_ubase, *p_temp;
    cudaGetSymbolAddress(&p_hist,  g_hist);
    cudaGetSymbolAddress(&p_off,   g_off);
    cudaGetSymbolAddress(&p_uniq,  g_uniq);
    cudaGetSymbolAddress(&p_ubase, g_ubase);
    cudaGetSymbolAddress(&p_temp,  g_temp);

    const int BLK = 256;
    int grid = (n + BLK - 1) / BLK;
    int nhalf = (n + 1) >> 1;
    int gridD = (nhalf + BLK - 1) / BLK;

    // 1) decode (2 pts/thread) + keys + bucket histogram + out_coords zero
    decode_kernel<<<gridD, BLK>>>(feats, coords, mask, W1, b1, W2, b2, W3, b3, out, n);

    // 2) multi-block exclusive scan of histogram -> bucket offsets
    size_t tb = 0;
    cub::DeviceScan::ExclusiveSum(nullptr, tb, (const uint32_t*)p_hist,
                                  (uint32_t*)p_off, NBUCKETS, (cudaStream_t)0);
    if (tb > 4u * 1024u * 1024u) return;
    cub::DeviceScan::ExclusiveSum(p_temp, tb, (const uint32_t*)p_hist,
                                  (uint32_t*)p_off, NBUCKETS, (cudaStream_t)0);

    // 2b) cursor init + hist reset + off[NBUCKETS]=n
    copyreset_kernel<<<NBUCKETS / BLK, BLK>>>(n);

    // 3) distribute into buckets
    distribute_kernel<<<grid, BLK>>>(n);

    // 4) per-bucket first-occurrence flags + unique counts (1 warp / bucket)
    uniq_kernel<<<NBUCKETS / WPB, WPB * 32>>>();

    // 5) multi-block exclusive scan of unique counts -> global rank bases
    size_t tb2 = 0;
    cub::DeviceScan::ExclusiveSum(nullptr, tb2, (const uint32_t*)p_uniq,
                                  (uint32_t*)p_ubase, NBUCKETS, (cudaStream_t)0);
    if (tb2 > 4u * 1024u * 1024u) return;
    cub::DeviceScan::ExclusiveSum(p_temp, tb2, (const uint32_t*)p_uniq,
                                  (uint32_t*)p_ubase, NBUCKETS, (cudaStream_t)0);

    // 6) ranks + inverse map + segment means (1 warp / bucket)
    finalize_kernel<<<NBUCKETS / WPB, WPB * 32>>>(out, n);
}

// round 9
// speedup vs baseline: 2.7565x; 1.1786x over previous
#include <cuda_runtime.h>
#include <cuda_bf16.h>
#include <cub/cub.cuh>
#include <cstdint>

#define NMAX 1000000
#define NBUCKETS 65536            // key bits 31..46
#define CAP 128                   // max bucket size (lambda ~15; >>10 sigma)
#define WPB 8                     // warps per block in rank kernel

// ---------------------------------------------------------------------------
// Static device scratch (no allocations allowed anywhere)
// ---------------------------------------------------------------------------
__device__ uint64_t g_keys[NMAX];        // decode output (unordered)
__device__ uint64_t g_bkeys[NMAX];       // bucket-distributed keys (+lrank+first)
__device__ uint32_t g_bvals[NMAX];       // bucket-distributed original indices
__device__ uint32_t g_hist[NBUCKETS];    // zero-init; reset by copyreset each call
__device__ uint32_t g_off[NBUCKETS + 1];
__device__ uint32_t g_cursor[NBUCKETS];
__device__ uint32_t g_uniq[NBUCKETS];
__device__ uint32_t g_ubase[NBUCKETS];
__device__ unsigned char g_temp[4u * 1024u * 1024u];

#define KEYMASK ((1ull << 47) - 1ull)
#define FIRSTBIT (1ull << 63)

// ---------------------------------------------------------------------------
// Packed f32x2 helpers (FFMA2 — PTX-only on sm_103a)
// ---------------------------------------------------------------------------
__device__ __forceinline__ void fma2(uint64_t& d, uint64_t a, uint64_t b, uint64_t c) {
    asm("fma.rn.f32x2 %0, %1, %2, %3;" : "=l"(d) : "l"(a), "l"(b), "l"(c));
}
__device__ __forceinline__ uint64_t dup2(float x) {
    uint64_t r; uint32_t u = __float_as_uint(x);
    asm("mov.b64 %0, {%1, %1};" : "=l"(r) : "r"(u));
    return r;
}
__device__ __forceinline__ uint64_t pack2(float lo, float hi) {
    uint64_t r;
    asm("mov.b64 %0, {%1, %2};" : "=l"(r) : "r"(__float_as_uint(lo)), "r"(__float_as_uint(hi)));
    return r;
}
__device__ __forceinline__ void unpack2(uint64_t v, float& lo, float& hi) {
    uint32_t a, b;
    asm("mov.b64 {%0, %1}, %2;" : "=r"(a), "=r"(b) : "l"(v));
    lo = __uint_as_float(a); hi = __uint_as_float(b);
}

// ---------------------------------------------------------------------------
// Kernel 1: MLP decode, TWO points per thread (i and i + n/2).
// Weight LDS.128 loads are shared between both points' FMA2 streams.
// ---------------------------------------------------------------------------
__global__ void __launch_bounds__(256)
decode_kernel(const float* __restrict__ feats,
              const int*   __restrict__ coords,
              const int*   __restrict__ mask,
              const float* __restrict__ W1, const float* __restrict__ b1,
              const float* __restrict__ W2, const float* __restrict__ b2,
              const float* __restrict__ W3, const float* __restrict__ b3,
              float* __restrict__ out, int n)
{
    __shared__ __align__(16) float sW1[64 * 32];
    __shared__ __align__(16) float sW2[32 * 16];
    __shared__ __align__(16) float sW3[16 * 3];
    __shared__ __align__(16) float sb1[32];
    __shared__ __align__(16) float sb2[16];
    __shared__ __align__(16) float sb3[4];

    for (int t = threadIdx.x; t < 64 * 32; t += blockDim.x) sW1[t] = W1[t];
    for (int t = threadIdx.x; t < 32 * 16; t += blockDim.x) sW2[t] = W2[t];
    for (int t = threadIdx.x; t < 16 * 3;  t += blockDim.x) sW3[t] = W3[t];
    if (threadIdx.x < 32) sb1[threadIdx.x] = b1[threadIdx.x];
    if (threadIdx.x < 16) sb2[threadIdx.x] = b2[threadIdx.x];
    if (threadIdx.x < 3)  sb3[threadIdx.x] = b3[threadIdx.x];
    __syncthreads();

    int nhalf = (n + 1) >> 1;
    int i = blockIdx.x * blockDim.x + threadIdx.x;
    if (i >= nhalf) return;
    int iA = i;
    int iB = i + nhalf;
    bool hasB = (iB < n);
    int iBs = hasB ? iB : iA;            // safe source for B-lane loads

    // ---- layer 1: 64 -> 32, two points, shared weight loads ----
    uint64_t accA[16], accB[16];
#pragma unroll
    for (int p = 0; p < 16; p++) {
        uint64_t b = pack2(sb1[2 * p], sb1[2 * p + 1]);
        accA[p] = b; accB[p] = b;
    }

    const ulonglong2* w1q = reinterpret_cast<const ulonglong2*>(sW1); // [64][8]
    const float4* fA = reinterpret_cast<const float4*>(feats) + (size_t)iA * 16;
    const float4* fB = reinterpret_cast<const float4*>(feats) + (size_t)iBs * 16;
#pragma unroll
    for (int k4 = 0; k4 < 16; k4++) {
        float4 fa = fA[k4];
        float4 fb = fB[k4];
        uint64_t a0 = dup2(fa.x), a1 = dup2(fa.y), a2 = dup2(fa.z), a3 = dup2(fa.w);
        uint64_t e0 = dup2(fb.x), e1 = dup2(fb.y), e2 = dup2(fb.z), e3 = dup2(fb.w);
        const ulonglong2* r0 = &w1q[(k4 * 4 + 0) * 8];
        const ulonglong2* r1 = &w1q[(k4 * 4 + 1) * 8];
        const ulonglong2* r2 = &w1q[(k4 * 4 + 2) * 8];
        const ulonglong2* r3 = &w1q[(k4 * 4 + 3) * 8];
#pragma unroll
        for (int q = 0; q < 8; q++) {
            ulonglong2 w;
            w = r0[q];
            fma2(accA[2*q], a0, w.x, accA[2*q]); fma2(accA[2*q+1], a0, w.y, accA[2*q+1]);
            fma2(accB[2*q], e0, w.x, accB[2*q]); fma2(accB[2*q+1], e0, w.y, accB[2*q+1]);
            w = r1[q];
            fma2(accA[2*q], a1, w.x, accA[2*q]); fma2(accA[2*q+1], a1, w.y, accA[2*q+1]);
            fma2(accB[2*q], e1, w.x, accB[2*q]); fma2(accB[2*q+1], e1, w.y, accB[2*q+1]);
            w = r2[q];
            fma2(accA[2*q], a2, w.x, accA[2*q]); fma2(accA[2*q+1], a2, w.y, accA[2*q+1]);
            fma2(accB[2*q], e2, w.x, accB[2*q]); fma2(accB[2*q+1], e2, w.y, accB[2*q+1]);
            w = r3[q];
            fma2(accA[2*q], a3, w.x, accA[2*q]); fma2(accA[2*q+1], a3, w.y, accA[2*q+1]);
            fma2(accB[2*q], e3, w.x, accB[2*q]); fma2(accB[2*q+1], e3, w.y, accB[2*q+1]);
        }
    }

    float h1A[32], h1B[32];
#pragma unroll
    for (int p = 0; p < 16; p++) {
        float lo, hi;
        unpack2(accA[p], lo, hi);
        h1A[2*p] = fmaxf(lo, 0.0f); h1A[2*p+1] = fmaxf(hi, 0.0f);
        unpack2(accB[p], lo, hi);
        h1B[2*p] = fmaxf(lo, 0.0f); h1B[2*p+1] = fmaxf(hi, 0.0f);
    }

    // ---- layer 2: 32 -> 16, two points, shared weight loads ----
    uint64_t ac2A[8], ac2B[8];
#pragma unroll
    for (int p = 0; p < 8; p++) {
        uint64_t b = pack2(sb2[2 * p], sb2[2 * p + 1]);
        ac2A[p] = b; ac2B[p] = b;
    }
    const ulonglong2* w2q = reinterpret_cast<const ulonglong2*>(sW2); // [32][4]
#pragma unroll
    for (int k = 0; k < 32; k++) {
        uint64_t a = dup2(h1A[k]);
        uint64_t e = dup2(h1B[k]);
        const ulonglong2* wr = &w2q[k * 4];
#pragma unroll
        for (int q = 0; q < 4; q++) {
            ulonglong2 w = wr[q];
            fma2(ac2A[2*q],   a, w.x, ac2A[2*q]);   fma2(ac2A[2*q+1], a, w.y, ac2A[2*q+1]);
            fma2(ac2B[2*q],   e, w.x, ac2B[2*q]);   fma2(ac2B[2*q+1], e, w.y, ac2B[2*q+1]);
        }
    }

    float h2A[16], h2B[16];
#pragma unroll
    for (int p = 0; p < 8; p++) {
        float lo, hi;
        unpack2(ac2A[p], lo, hi);
        h2A[2*p] = fmaxf(lo, 0.0f); h2A[2*p+1] = fmaxf(hi, 0.0f);
        unpack2(ac2B[p], lo, hi);
        h2B[2*p] = fmaxf(lo, 0.0f); h2B[2*p+1] = fmaxf(hi, 0.0f);
    }

    // ---- layer 3: 16 -> 3, two points ----
    float oA0 = sb3[0], oA1 = sb3[1], oA2 = sb3[2];
    float oB0 = sb3[0], oB1 = sb3[1], oB2 = sb3[2];
#pragma unroll
    for (int k = 0; k < 16; k++) {
        float w0 = sW3[k * 3 + 0], w1 = sW3[k * 3 + 1], w2 = sW3[k * 3 + 2];
        oA0 = fmaf(h2A[k], w0, oA0); oA1 = fmaf(h2A[k], w1, oA1); oA2 = fmaf(h2A[k], w2, oA2);
        oB0 = fmaf(h2B[k], w0, oB0); oB1 = fmaf(h2B[k], w1, oB1); oB2 = fmaf(h2B[k], w2, oB2);
    }

    // ---- epilogue per point (no g_newc, no zeroing: key encodes coords) ----
    {
        float m = (mask[iA] != 0) ? 1.0f : 0.0f;
        float o0 = oA0 * m, o1 = oA1 * m, o2 = oA2 * m;
        out[(size_t)3 * iA + 0] = o0;
        out[(size_t)3 * iA + 1] = o1;
        out[(size_t)3 * iA + 2] = o2;
        int4 c = reinterpret_cast<const int4*>(coords)[iA];
        int n1 = c.y + (int)rintf(o0);
        int n2 = c.z + (int)rintf(o1);
        int n3 = c.w + (int)rintf(o2);
        uint64_t key = ((uint64_t)(uint32_t)c.x         << 36)
                     | ((uint64_t)(uint32_t)(n1 + 1024) << 24)
                     | ((uint64_t)(uint32_t)(n2 + 1024) << 12)
                     |  (uint64_t)(uint32_t)(n3 + 1024);
        g_keys[iA] = key;
        atomicAdd(&g_hist[(uint32_t)(key >> 31)], 1u);
    }
    if (hasB) {
        float m = (mask[iB] != 0) ? 1.0f : 0.0f;
        float o0 = oB0 * m, o1 = oB1 * m, o2 = oB2 * m;
        out[(size_t)3 * iB + 0] = o0;
        out[(size_t)3 * iB + 1] = o1;
        out[(size_t)3 * iB + 2] = o2;
        int4 c = reinterpret_cast<const int4*>(coords)[iB];
        int n1 = c.y + (int)rintf(o0);
        int n2 = c.z + (int)rintf(o1);
        int n3 = c.w + (int)rintf(o2);
        uint64_t key = ((uint64_t)(uint32_t)c.x         << 36)
                     | ((uint64_t)(uint32_t)(n1 + 1024) << 24)
                     | ((uint64_t)(uint32_t)(n2 + 1024) << 12)
                     |  (uint64_t)(uint32_t)(n3 + 1024);
        g_keys[iB] = key;
        atomicAdd(&g_hist[(uint32_t)(key >> 31)], 1u);
    }
}

// ---------------------------------------------------------------------------
// Kernel 2b: cursor init + hist reset + sentinel (parallel, after cub scan)
// ---------------------------------------------------------------------------
__global__ void copyreset_kernel(int n)
{
    int i = blockIdx.x * blockDim.x + threadIdx.x;
    if (i >= NBUCKETS) return;
    g_cursor[i] = g_off[i];
    g_hist[i] = 0u;                       // replay determinism
    if (i == 0) g_off[NBUCKETS] = (uint32_t)n;
}

// ---------------------------------------------------------------------------
// Kernel 3: distribute (key, idx) into buckets
// ---------------------------------------------------------------------------
__global__ void distribute_kernel(int n)
{
    int i = blockIdx.x * blockDim.x + threadIdx.x;
    if (i >= n) return;
    uint64_t k = g_keys[i];
    uint32_t b = (uint32_t)(k >> 31);
    uint32_t pos = atomicAdd(&g_cursor[b], 1u);
    g_bkeys[pos] = k;
    g_bvals[pos] = (uint32_t)i;
}

// ---------------------------------------------------------------------------
// Kernel 4: per-bucket (one warp each): first-occurrence flags, local rank
// among distinct keys, unique count. lrank packed in bits 47..53, first in 63.
// ---------------------------------------------------------------------------
__global__ void __launch_bounds__(WPB * 32)
rank_kernel(void)
{
    __shared__ uint64_t sk[WPB][CAP];   // bit63 = first flag after pass 1

    int warp = threadIdx.x >> 5;
    int lane = threadIdx.x & 31;
    int b = blockIdx.x * WPB + warp;

    uint32_t start = g_off[b];
    int cnt = (int)(g_off[b + 1] - start);
    if (cnt == 0) { if (lane == 0) g_uniq[b] = 0; return; }
    if (cnt > CAP) cnt = CAP;   // unreachable statistically; keeps memory safe

    uint64_t* k = sk[warp];
    for (int p = lane; p < cnt; p += 32) k[p] = g_bkeys[start + p];
    __syncwarp();

    // pass 1: first-occurrence flags -> bit 63 in smem
    uint32_t u = 0;
    for (int p = lane; p < cnt; p += 32) {
        uint64_t key = k[p];
        bool first = true;
        for (int j = 0; j < p; j++)
            if ((k[j] & KEYMASK) == key) { first = false; break; }
        u += first ? 1u : 0u;
        if (first) k[p] = key | FIRSTBIT;   // lanes own disjoint p: no race
    }
    __syncwarp();

    // pass 2: local rank among distinct (count firsts with smaller key)
    for (int p = lane; p < cnt; p += 32) {
        uint64_t kp = k[p];
        uint64_t myk = kp & KEYMASK;
        uint32_t less = 0;
        for (int j = 0; j < cnt; j++) {
            uint64_t kj = k[j];
            less += (uint32_t)(((kj & KEYMASK) < myk) & (kj >> 63));
        }
        g_bkeys[start + p] = (kp & (FIRSTBIT | KEYMASK)) | ((uint64_t)less << 47);
    }

#pragma unroll
    for (int d = 16; d > 0; d >>= 1)
        u += __shfl_down_sync(0xFFFFFFFFu, u, d);
    if (lane == 0) g_uniq[b] = u;
}

// ---------------------------------------------------------------------------
// Kernel 5: O(n) map: inv = ubase + lrank; firsts write out_coords decoded
// from the key; rows >= total_uniq are zeroed.
// ---------------------------------------------------------------------------
__global__ void map_kernel(float* __restrict__ out, int n)
{
    int p = blockIdx.x * blockDim.x + threadIdx.x;
    if (p >= n) return;

    uint32_t total = g_ubase[NBUCKETS - 1] + g_uniq[NBUCKETS - 1];

    // zero tail rows of out_coords (row index == p); ~n - total ~ 100 rows
    if ((uint32_t)p >= total)
        reinterpret_cast<float4*>(out + (size_t)3 * n)[p] =
            make_float4(0.f, 0.f, 0.f, 0.f);

    uint64_t kp = g_bkeys[p];
    uint32_t b = (uint32_t)(kp >> 31) & 0xFFFFu;
    uint32_t r = g_ubase[b] + (uint32_t)((kp >> 47) & 0x7Fu);
    uint32_t orig = g_bvals[p];

    // inv map (float32) at offset 7n
    out[(size_t)7 * n + orig] = (float)r;

    if (kp & FIRSTBIT) {
        // equal keys => identical new_coords; mean == the coords themselves
        float cx = (float)(int)((kp >> 36) & 0x7FFu);
        float c1 = (float)((int)((kp >> 24) & 0xFFFu) - 1024);
        float c2 = (float)((int)((kp >> 12) & 0xFFFu) - 1024);
        float c3 = (float)((int)( kp        & 0xFFFu) - 1024);
        reinterpret_cast<float4*>(out + (size_t)3 * n)[r] =
            make_float4(cx, c1, c2, c3);
    }
}

// ---------------------------------------------------------------------------
// Host launch
// ---------------------------------------------------------------------------
extern "C" void kernel_launch(void* const* d_in, const int* in_sizes, int n_in,
                              void* d_out, int out_size)
{
    const float* feats  = (const float*)d_in[0];
    const int*   coords = (const int*)d_in[1];
    const int*   mask   = (const int*)d_in[2];
    const float* W1 = (const float*)d_in[3];
    const float* b1 = (const float*)d_in[4];
    const float* W2 = (const float*)d_in[5];
    const float* b2 = (const float*)d_in[6];
    const float* W3 = (const float*)d_in[7];
    const float* b3 = (const float*)d_in[8];
    float* out = (float*)d_out;

    int n = in_sizes[0] / 64;
    if (n > NMAX) n = NMAX;

    void *p_hist, *p_off, *p_uniq, *p_ubase, *p_temp;
    cudaGetSymbolAddress(&p_hist,  g_hist);
    cudaGetSymbolAddress(&p_off,   g_off);
    cudaGetSymbolAddress(&p_uniq,  g_uniq);
    cudaGetSymbolAddress(&p_ubase, g_ubase);
    cudaGetSymbolAddress(&p_temp,  g_temp);

    const int BLK = 256;
    int grid = (n + BLK - 1) / BLK;
    int nhalf = (n + 1) >> 1;
    int gridD = (nhalf + BLK - 1) / BLK;

    // 1) decode (2 pts/thread) + keys + bucket histogram
    decode_kernel<<<gridD, BLK>>>(feats, coords, mask, W1, b1, W2, b2, W3, b3, out, n);

    // 2) multi-block exclusive scan of histogram -> bucket offsets
    size_t tb = 0;
    cub::DeviceScan::ExclusiveSum(nullptr, tb, (const uint32_t*)p_hist,
                                  (uint32_t*)p_off, NBUCKETS, (cudaStream_t)0);
    if (tb > 4u * 1024u * 1024u) return;
    cub::DeviceScan::ExclusiveSum(p_temp, tb, (const uint32_t*)p_hist,
                                  (uint32_t*)p_off, NBUCKETS, (cudaStream_t)0);

    // 2b) cursor init + hist reset + off[NBUCKETS]=n
    copyreset_kernel<<<NBUCKETS / BLK, BLK>>>(n);

    // 3) distribute into buckets
    distribute_kernel<<<grid, BLK>>>(n);

    // 4) per-bucket flags + local ranks + unique counts (1 warp / bucket)
    rank_kernel<<<NBUCKETS / WPB, WPB * 32>>>();

    // 5) multi-block exclusive scan of unique counts -> global rank bases
    size_t tb2 = 0;
    cub::DeviceScan::ExclusiveSum(nullptr, tb2, (const uint32_t*)p_uniq,
                                  (uint32_t*)p_ubase, NBUCKETS, (cudaStream_t)0);
    if (tb2 > 4u * 1024u * 1024u) return;
    cub::DeviceScan::ExclusiveSum(p_temp, tb2, (const uint32_t*)p_uniq,
                                  (uint32_t*)p_ubase, NBUCKETS, (cudaStream_t)0);

    // 6) O(n) map: inv + out_coords + tail zeroing
    map_kernel<<<grid, BLK>>>(out, n);
}

// round 10
// speedup vs baseline: 2.8656x; 1.0396x over previous
#include <cuda_runtime.h>
#include <cuda_bf16.h>
#include <cub/cub.cuh>
#include <cstdint>

#define NMAX 1000000
#define NBUCKETS 65536            // key bits 31..46
#define CAP 128                   // max bucket size (lambda ~15; >>10 sigma)
#define WPB 8                     // warps per block in rank kernel

// ---------------------------------------------------------------------------
// Static device scratch (no allocations allowed anywhere)
// ---------------------------------------------------------------------------
__device__ uint64_t   g_keys[NMAX];        // decode output: key | (lidx<<47)
__device__ ulonglong2 g_bpairs[NMAX];      // bucket-ordered {key(+lrank+first), orig idx}
__device__ uint32_t   g_hist[NBUCKETS + 1];// zero-init; [NBUCKETS] stays 0; reset by map
__device__ uint32_t   g_off[NBUCKETS + 1];
__device__ uint32_t   g_uniq[NBUCKETS];
__device__ uint32_t   g_ubase[NBUCKETS];
__device__ unsigned char g_temp[4u * 1024u * 1024u];

#define KEYMASK ((1ull << 47) - 1ull)
#define FIRSTBIT (1ull << 63)

// ---------------------------------------------------------------------------
// Packed f32x2 helpers (FFMA2 — PTX-only on sm_103a)
// ---------------------------------------------------------------------------
__device__ __forceinline__ void fma2(uint64_t& d, uint64_t a, uint64_t b, uint64_t c) {
    asm("fma.rn.f32x2 %0, %1, %2, %3;" : "=l"(d) : "l"(a), "l"(b), "l"(c));
}
__device__ __forceinline__ uint64_t dup2(float x) {
    uint64_t r; uint32_t u = __float_as_uint(x);
    asm("mov.b64 %0, {%1, %1};" : "=l"(r) : "r"(u));
    return r;
}
__device__ __forceinline__ uint64_t pack2(float lo, float hi) {
    uint64_t r;
    asm("mov.b64 %0, {%1, %2};" : "=l"(r) : "r"(__float_as_uint(lo)), "r"(__float_as_uint(hi)));
    return r;
}
__device__ __forceinline__ void unpack2(uint64_t v, float& lo, float& hi) {
    uint32_t a, b;
    asm("mov.b64 {%0, %1}, %2;" : "=r"(a), "=r"(b) : "l"(v));
    lo = __uint_as_float(a); hi = __uint_as_float(b);
}

// ---------------------------------------------------------------------------
// Kernel 1: MLP decode, TWO points per thread (i and i + n/2).
// Weight LDS.128 loads are shared between both points' FMA2 streams.
// Epilogue: key build + bucket slot reservation (lidx packed in bits 47..54).
// ---------------------------------------------------------------------------
__global__ void __launch_bounds__(256)
decode_kernel(const float* __restrict__ feats,
              const int*   __restrict__ coords,
              const int*   __restrict__ mask,
              const float* __restrict__ W1, const float* __restrict__ b1,
              const float* __restrict__ W2, const float* __restrict__ b2,
              const float* __restrict__ W3, const float* __restrict__ b3,
              float* __restrict__ out, int n)
{
    __shared__ __align__(16) float sW1[64 * 32];
    __shared__ __align__(16) float sW2[32 * 16];
    __shared__ __align__(16) float sW3[16 * 3];
    __shared__ __align__(16) float sb1[32];
    __shared__ __align__(16) float sb2[16];
    __shared__ __align__(16) float sb3[4];

    for (int t = threadIdx.x; t < 64 * 32; t += blockDim.x) sW1[t] = W1[t];
    for (int t = threadIdx.x; t < 32 * 16; t += blockDim.x) sW2[t] = W2[t];
    for (int t = threadIdx.x; t < 16 * 3;  t += blockDim.x) sW3[t] = W3[t];
    if (threadIdx.x < 32) sb1[threadIdx.x] = b1[threadIdx.x];
    if (threadIdx.x < 16) sb2[threadIdx.x] = b2[threadIdx.x];
    if (threadIdx.x < 3)  sb3[threadIdx.x] = b3[threadIdx.x];
    __syncthreads();

    int nhalf = (n + 1) >> 1;
    int i = blockIdx.x * blockDim.x + threadIdx.x;
    if (i >= nhalf) return;
    int iA = i;
    int iB = i + nhalf;
    bool hasB = (iB < n);
    int iBs = hasB ? iB : iA;            // safe source for B-lane loads

    // ---- layer 1: 64 -> 32, two points, shared weight loads ----
    uint64_t accA[16], accB[16];
#pragma unroll
    for (int p = 0; p < 16; p++) {
        uint64_t b = pack2(sb1[2 * p], sb1[2 * p + 1]);
        accA[p] = b; accB[p] = b;
    }

    const ulonglong2* w1q = reinterpret_cast<const ulonglong2*>(sW1); // [64][8]
    const float4* fA = reinterpret_cast<const float4*>(feats) + (size_t)iA * 16;
    const float4* fB = reinterpret_cast<const float4*>(feats) + (size_t)iBs * 16;
#pragma unroll
    for (int k4 = 0; k4 < 16; k4++) {
        float4 fa = fA[k4];
        float4 fb = fB[k4];
        uint64_t a0 = dup2(fa.x), a1 = dup2(fa.y), a2 = dup2(fa.z), a3 = dup2(fa.w);
        uint64_t e0 = dup2(fb.x), e1 = dup2(fb.y), e2 = dup2(fb.z), e3 = dup2(fb.w);
        const ulonglong2* r0 = &w1q[(k4 * 4 + 0) * 8];
        const ulonglong2* r1 = &w1q[(k4 * 4 + 1) * 8];
        const ulonglong2* r2 = &w1q[(k4 * 4 + 2) * 8];
        const ulonglong2* r3 = &w1q[(k4 * 4 + 3) * 8];
#pragma unroll
        for (int q = 0; q < 8; q++) {
            ulonglong2 w;
            w = r0[q];
            fma2(accA[2*q], a0, w.x, accA[2*q]); fma2(accA[2*q+1], a0, w.y, accA[2*q+1]);
            fma2(accB[2*q], e0, w.x, accB[2*q]); fma2(accB[2*q+1], e0, w.y, accB[2*q+1]);
            w = r1[q];
            fma2(accA[2*q], a1, w.x, accA[2*q]); fma2(accA[2*q+1], a1, w.y, accA[2*q+1]);
            fma2(accB[2*q], e1, w.x, accB[2*q]); fma2(accB[2*q+1], e1, w.y, accB[2*q+1]);
            w = r2[q];
            fma2(accA[2*q], a2, w.x, accA[2*q]); fma2(accA[2*q+1], a2, w.y, accA[2*q+1]);
            fma2(accB[2*q], e2, w.x, accB[2*q]); fma2(accB[2*q+1], e2, w.y, accB[2*q+1]);
            w = r3[q];
            fma2(accA[2*q], a3, w.x, accA[2*q]); fma2(accA[2*q+1], a3, w.y, accA[2*q+1]);
            fma2(accB[2*q], e3, w.x, accB[2*q]); fma2(accB[2*q+1], e3, w.y, accB[2*q+1]);
        }
    }

    float h1A[32], h1B[32];
#pragma unroll
    for (int p = 0; p < 16; p++) {
        float lo, hi;
        unpack2(accA[p], lo, hi);
        h1A[2*p] = fmaxf(lo, 0.0f); h1A[2*p+1] = fmaxf(hi, 0.0f);
        unpack2(accB[p], lo, hi);
        h1B[2*p] = fmaxf(lo, 0.0f); h1B[2*p+1] = fmaxf(hi, 0.0f);
    }

    // ---- layer 2: 32 -> 16, two points, shared weight loads ----
    uint64_t ac2A[8], ac2B[8];
#pragma unroll
    for (int p = 0; p < 8; p++) {
        uint64_t b = pack2(sb2[2 * p], sb2[2 * p + 1]);
        ac2A[p] = b; ac2B[p] = b;
    }
    const ulonglong2* w2q = reinterpret_cast<const ulonglong2*>(sW2); // [32][4]
#pragma unroll
    for (int k = 0; k < 32; k++) {
        uint64_t a = dup2(h1A[k]);
        uint64_t e = dup2(h1B[k]);
        const ulonglong2* wr = &w2q[k * 4];
#pragma unroll
        for (int q = 0; q < 4; q++) {
            ulonglong2 w = wr[q];
            fma2(ac2A[2*q],   a, w.x, ac2A[2*q]);   fma2(ac2A[2*q+1], a, w.y, ac2A[2*q+1]);
            fma2(ac2B[2*q],   e, w.x, ac2B[2*q]);   fma2(ac2B[2*q+1], e, w.y, ac2B[2*q+1]);
        }
    }

    float h2A[16], h2B[16];
#pragma unroll
    for (int p = 0; p < 8; p++) {
        float lo, hi;
        unpack2(ac2A[p], lo, hi);
        h2A[2*p] = fmaxf(lo, 0.0f); h2A[2*p+1] = fmaxf(hi, 0.0f);
        unpack2(ac2B[p], lo, hi);
        h2B[2*p] = fmaxf(lo, 0.0f); h2B[2*p+1] = fmaxf(hi, 0.0f);
    }

    // ---- layer 3: 16 -> 3, two points ----
    float oA0 = sb3[0], oA1 = sb3[1], oA2 = sb3[2];
    float oB0 = sb3[0], oB1 = sb3[1], oB2 = sb3[2];
#pragma unroll
    for (int k = 0; k < 16; k++) {
        float w0 = sW3[k * 3 + 0], w1 = sW3[k * 3 + 1], w2 = sW3[k * 3 + 2];
        oA0 = fmaf(h2A[k], w0, oA0); oA1 = fmaf(h2A[k], w1, oA1); oA2 = fmaf(h2A[k], w2, oA2);
        oB0 = fmaf(h2B[k], w0, oB0); oB1 = fmaf(h2B[k], w1, oB1); oB2 = fmaf(h2B[k], w2, oB2);
    }

    // ---- epilogue per point ----
    {
        float m = (mask[iA] != 0) ? 1.0f : 0.0f;
        float o0 = oA0 * m, o1 = oA1 * m, o2 = oA2 * m;
        out[(size_t)3 * iA + 0] = o0;
        out[(size_t)3 * iA + 1] = o1;
        out[(size_t)3 * iA + 2] = o2;
        int4 c = reinterpret_cast<const int4*>(coords)[iA];
        int n1 = c.y + (int)rintf(o0);
        int n2 = c.z + (int)rintf(o1);
        int n3 = c.w + (int)rintf(o2);
        uint64_t key = ((uint64_t)(uint32_t)c.x         << 36)
                     | ((uint64_t)(uint32_t)(n1 + 1024) << 24)
                     | ((uint64_t)(uint32_t)(n2 + 1024) << 12)
                     |  (uint64_t)(uint32_t)(n3 + 1024);
        uint32_t lidx = atomicAdd(&g_hist[(uint32_t)(key >> 31)], 1u);
        g_keys[iA] = key | ((uint64_t)(lidx & 0xFFu) << 47);
    }
    if (hasB) {
        float m = (mask[iB] != 0) ? 1.0f : 0.0f;
        float o0 = oB0 * m, o1 = oB1 * m, o2 = oB2 * m;
        out[(size_t)3 * iB + 0] = o0;
        out[(size_t)3 * iB + 1] = o1;
        out[(size_t)3 * iB + 2] = o2;
        int4 c = reinterpret_cast<const int4*>(coords)[iB];
        int n1 = c.y + (int)rintf(o0);
        int n2 = c.z + (int)rintf(o1);
        int n3 = c.w + (int)rintf(o2);
        uint64_t key = ((uint64_t)(uint32_t)c.x         << 36)
                     | ((uint64_t)(uint32_t)(n1 + 1024) << 24)
                     | ((uint64_t)(uint32_t)(n2 + 1024) << 12)
                     |  (uint64_t)(uint32_t)(n3 + 1024);
        uint32_t lidx = atomicAdd(&g_hist[(uint32_t)(key >> 31)], 1u);
        g_keys[iB] = key | ((uint64_t)(lidx & 0xFFu) << 47);
    }
}

// ---------------------------------------------------------------------------
// Kernel 2: atomic-free distribute: pos = off[bucket] + lidx (from key bits)
// Single 16B pair store per element (one 32B sector).
// ---------------------------------------------------------------------------
__global__ void distribute_kernel(int n)
{
    int i = blockIdx.x * blockDim.x + threadIdx.x;
    if (i >= n) return;
    uint64_t k = g_keys[i];
    uint32_t b = (uint32_t)(k >> 31) & 0xFFFFu;
    uint32_t pos = g_off[b] + (uint32_t)((k >> 47) & 0xFFu);
    ulonglong2 pr;
    pr.x = k & KEYMASK;                 // strip lidx
    pr.y = (uint64_t)(uint32_t)i;
    g_bpairs[pos] = pr;
}

// ---------------------------------------------------------------------------
// Kernel 3: per-bucket (one warp each): first-occurrence flags, local rank
// among distinct keys, unique count. lrank packed in bits 47..54, first in 63.
// ---------------------------------------------------------------------------
__global__ void __launch_bounds__(WPB * 32)
rank_kernel(void)
{
    __shared__ uint64_t sk[WPB][CAP];   // bit63 = first flag after pass 1

    int warp = threadIdx.x >> 5;
    int lane = threadIdx.x & 31;
    int b = blockIdx.x * WPB + warp;

    uint32_t start = g_off[b];
    int cnt = (int)(g_off[b + 1] - start);
    if (cnt == 0) { if (lane == 0) g_uniq[b] = 0; return; }
    if (cnt > CAP) cnt = CAP;   // unreachable statistically; keeps memory safe

    uint64_t* k = sk[warp];
    for (int p = lane; p < cnt; p += 32) k[p] = g_bpairs[start + p].x;
    __syncwarp();

    // pass 1: first-occurrence flags -> bit 63 in smem
    uint32_t u = 0;
    for (int p = lane; p < cnt; p += 32) {
        uint64_t key = k[p];
        bool first = true;
        for (int j = 0; j < p; j++)
            if ((k[j] & KEYMASK) == key) { first = false; break; }
        u += first ? 1u : 0u;
        if (first) k[p] = key | FIRSTBIT;   // lanes own disjoint p: no race
    }
    __syncwarp();

    // pass 2: local rank among distinct (count firsts with smaller key)
    for (int p = lane; p < cnt; p += 32) {
        uint64_t kp = k[p];
        uint64_t myk = kp & KEYMASK;
        uint32_t less = 0;
        for (int j = 0; j < cnt; j++) {
            uint64_t kj = k[j];
            less += (uint32_t)(((kj & KEYMASK) < myk) & (kj >> 63));
        }
        g_bpairs[start + p].x =
            (kp & (FIRSTBIT | KEYMASK)) | ((uint64_t)less << 47);
    }

#pragma unroll
    for (int d = 16; d > 0; d >>= 1)
        u += __shfl_down_sync(0xFFFFFFFFu, u, d);
    if (lane == 0) g_uniq[b] = u;
}

// ---------------------------------------------------------------------------
// Kernel 4: O(n) map: inv = ubase + lrank; firsts write out_coords decoded
// from the key; rows >= total_uniq zeroed; hist reset for graph replay.
// ---------------------------------------------------------------------------
__global__ void map_kernel(float* __restrict__ out, int n)
{
    int p = blockIdx.x * blockDim.x + threadIdx.x;
    if (p >= n) return;

    // reset histogram for the next replay (bucket count + sentinel)
    if (p <= NBUCKETS) g_hist[p] = 0u;

    uint32_t total = g_ubase[NBUCKETS - 1] + g_uniq[NBUCKETS - 1];

    // zero tail rows of out_coords (row index == p); ~n - total ~ few hundred
    if ((uint32_t)p >= total)
        reinterpret_cast<float4*>(out + (size_t)3 * n)[p] =
            make_float4(0.f, 0.f, 0.f, 0.f);

    ulonglong2 pr = g_bpairs[p];
    uint64_t kp = pr.x;
    uint32_t b = (uint32_t)(kp >> 31) & 0xFFFFu;
    uint32_t r = g_ubase[b] + (uint32_t)((kp >> 47) & 0xFFu);
    uint32_t orig = (uint32_t)pr.y;

    // inv map (float32) at offset 7n
    out[(size_t)7 * n + orig] = (float)r;

    if (kp & FIRSTBIT) {
        // equal keys => identical new_coords; mean == the coords themselves
        float cx = (float)(int)((kp >> 36) & 0x7FFu);
        float c1 = (float)((int)((kp >> 24) & 0xFFFu) - 1024);
        float c2 = (float)((int)((kp >> 12) & 0xFFFu) - 1024);
        float c3 = (float)((int)( kp        & 0xFFFu) - 1024);
        reinterpret_cast<float4*>(out + (size_t)3 * n)[r] =
            make_float4(cx, c1, c2, c3);
    }
}

// ---------------------------------------------------------------------------
// Host launch
// ---------------------------------------------------------------------------
extern "C" void kernel_launch(void* const* d_in, const int* in_sizes, int n_in,
                              void* d_out, int out_size)
{
    const float* feats  = (const float*)d_in[0];
    const int*   coords = (const int*)d_in[1];
    const int*   mask   = (const int*)d_in[2];
    const float* W1 = (const float*)d_in[3];
    const float* b1 = (const float*)d_in[4];
    const float* W2 = (const float*)d_in[5];
    const float* b2 = (const float*)d_in[6];
    const float* W3 = (const float*)d_in[7];
    const float* b3 = (const float*)d_in[8];
    float* out = (float*)d_out;

    int n = in_sizes[0] / 64;
    if (n > NMAX) n = NMAX;

    void *p_hist, *p_off, *p_uniq, *p_ubase, *p_temp;
    cudaGetSymbolAddress(&p_hist,  g_hist);
    cudaGetSymbolAddress(&p_off,   g_off);
    cudaGetSymbolAddress(&p_uniq,  g_uniq);
    cudaGetSymbolAddress(&p_ubase, g_ubase);
    cudaGetSymbolAddress(&p_temp,  g_temp);

    const int BLK = 256;
    int grid = (n + BLK - 1) / BLK;
    int nhalf = (n + 1) >> 1;
    int gridD = (nhalf + BLK - 1) / BLK;

    // 1) decode (2 pts/thread) + keys + bucket histogram + slot reservation
    decode_kernel<<<gridD, BLK>>>(feats, coords, mask, W1, b1, W2, b2, W3, b3, out, n);

    // 2) exclusive scan of histogram (incl. zero sentinel) -> off[0..NBUCKETS]
    size_t tb = 0;
    cub::DeviceScan::ExclusiveSum(nullptr, tb, (const uint32_t*)p_hist,
                                  (uint32_t*)p_off, NBUCKETS + 1, (cudaStream_t)0);
    if (tb > 4u * 1024u * 1024u) return;
    cub::DeviceScan::ExclusiveSum(p_temp, tb, (const uint32_t*)p_hist,
                                  (uint32_t*)p_off, NBUCKETS + 1, (cudaStream_t)0);

    // 3) atomic-free distribute into buckets (16B pair stores)
    distribute_kernel<<<grid, BLK>>>(n);

    // 4) per-bucket flags + local ranks + unique counts (1 warp / bucket)
    rank_kernel<<<NBUCKETS / WPB, WPB * 32>>>();

    // 5) exclusive scan of unique counts -> global rank bases
    size_t tb2 = 0;
    cub::DeviceScan::ExclusiveSum(nullptr, tb2, (const uint32_t*)p_uniq,
                                  (uint32_t*)p_ubase, NBUCKETS, (cudaStream_t)0);
    if (tb2 > 4u * 1024u * 1024u) return;
    cub::DeviceScan::ExclusiveSum(p_temp, tb2, (const uint32_t*)p_uniq,
                                  (uint32_t*)p_ubase, NBUCKETS, (cudaStream_t)0);

    // 6) O(n) map: inv + out_coords + tail zeroing + hist reset
    map_kernel<<<grid, BLK>>>(out, n);
}